// round 5
// baseline (speedup 1.0000x reference)
#include <cuda_runtime.h>

#define NN 2048
#define FEAT 64
#define HID 16
#define C 8
#define NG 64
#define ROWS_PER_TASK 64   // 2048/32 row-blocks, 64 m-chunks -> 2048 warp tasks

// scratch (allocation-free rule: device globals)
__device__ __align__(16) float g_node[NN * C];   // 64 KB, per-node summed feature MLP
__device__ __align__(16) float e_tab[11 * C];    // rho-MLP table for dist = 0..10

// ---------------------------------------------------------------------------
// Kernel 1: g[n,c] = sum_f ( sum_h relu(x[n,f]*w1[f,h]+b1[f,h]) * w2[f,h,c] + b2[f,c] )
// Block = 64 threads (one per feature), grid = 2048 (one per node).
// Block 0 additionally builds the e-table and zeroes d_out.
// ---------------------------------------------------------------------------
__global__ void __launch_bounds__(FEAT) tgnan_k1(
    const float* __restrict__ x,
    const float* __restrict__ w1, const float* __restrict__ b1,
    const float* __restrict__ w2, const float* __restrict__ b2,
    const float* __restrict__ rw1, const float* __restrict__ rb1,
    const float* __restrict__ rw2, const float* __restrict__ rb2,
    float* __restrict__ out)
{
    const int n = blockIdx.x;
    const int f = threadIdx.x;           // 0..63

    const float xv = x[n * FEAT + f];
    float acc[C];
#pragma unroll
    for (int c = 0; c < C; c++) acc[c] = b2[f * C + c];

#pragma unroll
    for (int h = 0; h < HID; h++) {
        const float hv = fmaxf(fmaf(xv, w1[f * HID + h], b1[f * HID + h]), 0.0f);
        const float4* wp = reinterpret_cast<const float4*>(w2 + (size_t)(f * HID + h) * C);
        const float4 wa = __ldg(wp);
        const float4 wb = __ldg(wp + 1);
        acc[0] = fmaf(hv, wa.x, acc[0]);
        acc[1] = fmaf(hv, wa.y, acc[1]);
        acc[2] = fmaf(hv, wa.z, acc[2]);
        acc[3] = fmaf(hv, wa.w, acc[3]);
        acc[4] = fmaf(hv, wb.x, acc[4]);
        acc[5] = fmaf(hv, wb.y, acc[5]);
        acc[6] = fmaf(hv, wb.z, acc[6]);
        acc[7] = fmaf(hv, wb.w, acc[7]);
    }

    // reduce over the 64 features: warp butterfly, then cross-warp via smem
#pragma unroll
    for (int off = 16; off; off >>= 1)
#pragma unroll
        for (int c = 0; c < C; c++)
            acc[c] += __shfl_xor_sync(0xffffffffu, acc[c], off);

    __shared__ float red[2][C];
    if ((f & 31) == 0) {
#pragma unroll
        for (int c = 0; c < C; c++) red[f >> 5][c] = acc[c];
    }
    __syncthreads();
    if (f < C) g_node[n * C + f] = red[0][f] + red[1][f];

    if (n == 0) {
        // e-table: rho MLP evaluated at dist = 0..10 (dist = -1 contributes 0)
        if (f < 11) {
            const float dd = (float)f;
            float a2[C];
#pragma unroll
            for (int c = 0; c < C; c++) a2[c] = rb2[c];
#pragma unroll
            for (int h = 0; h < HID; h++) {
                const float hv = fmaxf(fmaf(dd, rw1[h], rb1[h]), 0.0f);
#pragma unroll
                for (int c = 0; c < C; c++)
                    a2[c] = fmaf(hv, rw2[h * C + c], a2[c]);
            }
#pragma unroll
            for (int c = 0; c < C; c++) e_tab[f * C + c] = a2[c];
        }
        // zero output (d_out is poisoned; k2 accumulates atomically)
        for (int i = f; i < NG * C; i += FEAT) out[i] = 0.0f;
    }
}

// ---------------------------------------------------------------------------
// Kernel 2: out[b,c] += sum_m g[m,c] * sum_{n in b} e[dist(n,m), c]
// Warp task = 32 consecutive m (lane = m) x 64 consecutive rows n.
// Per (lane, current-graph): 12x5-bit packed histogram of dist values in u64;
// flushed (<=31 rows / graph boundary) into fp32 A[c] using register e-table.
// ---------------------------------------------------------------------------
__device__ __forceinline__ void flush_hist(unsigned long long& hist,
                                           float A[C], const float er[11][C])
{
#pragma unroll
    for (int d = 0; d < 11; d++) {
        // slot (d+1) holds count of dist==d; slot 0 (dist==-1) contributes 0
        const unsigned int cnt = (unsigned int)(hist >> (5 * (d + 1))) & 31u;
        const float fc = (float)cnt;
#pragma unroll
        for (int c = 0; c < C; c++) A[c] = fmaf(fc, er[d][c], A[c]);
    }
    hist = 0ull;
}

__device__ __forceinline__ void emit_graph(const float A[C], const float gv[C],
                                           int gb, int lane, float* __restrict__ out)
{
    float p[C];
#pragma unroll
    for (int c = 0; c < C; c++) p[c] = A[c] * gv[c];
#pragma unroll
    for (int off = 16; off; off >>= 1)
#pragma unroll
        for (int c = 0; c < C; c++)
            p[c] += __shfl_xor_sync(0xffffffffu, p[c], off);
    if (lane == 0) {
#pragma unroll
        for (int c = 0; c < C; c++) atomicAdd(out + gb * C + c, p[c]);
    }
}

__global__ void __launch_bounds__(128) tgnan_k2(
    const float* __restrict__ dist,
    const int* __restrict__ batch,
    float* __restrict__ out)
{
    const int w    = (blockIdx.x * 128 + threadIdx.x) >> 5;  // 0..2047
    const int lane = threadIdx.x & 31;
    const int mc   = w & 63;          // m-chunk
    const int rb   = w >> 6;          // row-block
    const int m    = mc * 32 + lane;
    const int r0   = rb * ROWS_PER_TASK;

    // e-table into registers (88 regs, statically indexed everywhere)
    float er[11][C];
#pragma unroll
    for (int d = 0; d < 11; d++) {
        const float4* ep = reinterpret_cast<const float4*>(e_tab + d * C);
        const float4 ea = ep[0];
        const float4 eb = ep[1];
        er[d][0] = ea.x; er[d][1] = ea.y; er[d][2] = ea.z; er[d][3] = ea.w;
        er[d][4] = eb.x; er[d][5] = eb.y; er[d][6] = eb.z; er[d][7] = eb.w;
    }
    // g row for this lane's m (constant across the whole task)
    float gv[C];
    {
        const float4* gp = reinterpret_cast<const float4*>(g_node + (size_t)m * C);
        const float4 ga = gp[0];
        const float4 gb4 = gp[1];
        gv[0] = ga.x; gv[1] = ga.y; gv[2] = ga.z; gv[3] = ga.w;
        gv[4] = gb4.x; gv[5] = gb4.y; gv[6] = gb4.z; gv[7] = gb4.w;
    }

    float A[C];
#pragma unroll
    for (int c = 0; c < C; c++) A[c] = 0.0f;
    unsigned long long hist = 0ull;
    int cur_g = __ldg(batch + r0);
    int cnt = 0;

    const float* pd = dist + (size_t)r0 * NN + m;
    for (int n = 0; n < ROWS_PER_TASK; n++) {
        const int gid = __ldg(batch + r0 + n);   // warp-uniform broadcast
        if (gid != cur_g) {
            flush_hist(hist, A, er);
            cnt = 0;
            emit_graph(A, gv, cur_g, lane, out);
#pragma unroll
            for (int c = 0; c < C; c++) A[c] = 0.0f;
            cur_g = gid;
        }
        const float fd = __ldg(pd);
        pd += NN;
        int di = (int)fd + 1;                    // -1..10 -> 0..11
        di = max(0, min(11, di));                // safety clamp
        hist += 1ull << (di * 5);                // 12 x 5-bit fields, max 31 each
        if (++cnt == 31) {
            flush_hist(hist, A, er);
            cnt = 0;
        }
    }
    flush_hist(hist, A, er);
    emit_graph(A, gv, cur_g, lane, out);
}

// ---------------------------------------------------------------------------
extern "C" void kernel_launch(void* const* d_in, const int* in_sizes, int n_in,
                              void* d_out, int out_size)
{
    const float* x    = (const float*)d_in[0];
    const float* dist = (const float*)d_in[1];
    const int*   bv   = (const int*)d_in[2];
    const float* fw1  = (const float*)d_in[3];
    const float* fb1  = (const float*)d_in[4];
    const float* fw2  = (const float*)d_in[5];
    const float* fb2  = (const float*)d_in[6];
    const float* rw1  = (const float*)d_in[7];
    const float* rb1  = (const float*)d_in[8];
    const float* rw2  = (const float*)d_in[9];
    const float* rb2  = (const float*)d_in[10];
    float* out = (float*)d_out;

    tgnan_k1<<<NN, FEAT>>>(x, fw1, fb1, fw2, fb2, rw1, rb1, rw2, rb2, out);
    tgnan_k2<<<512, 128>>>(dist, bv, out);
}